// round 10
// baseline (speedup 1.0000x reference)
#include <cuda_runtime.h>
#include <cuda_bf16.h>
#include <cstdint>

#define B_    128
#define H_    14
#define W_    14
#define C4_   128           // C/4
#define NCLS_ 200
#define HWN_  196
#define TILE_ 32            // 6 full tiles + ragged tile of 4
#define NT_   7
#define TSTR_ 132           // row stride (floats): 528 B, 16B multiple -> aligned LDS.128
#define THR_  512
#define NWRP_ 16

__device__ __forceinline__ void cp_async4(unsigned dst, const void* src, bool p) {
    if (p) asm volatile("cp.async.ca.shared.global [%0], [%1], 4;" :: "r"(dst), "l"(src));
}
__device__ __forceinline__ void cp_commit() {
    asm volatile("cp.async.commit_group;" ::: "memory");
}
template <int N> __device__ __forceinline__ void cp_wait() {
    asm volatile("cp.async.wait_group %0;" :: "n"(N) : "memory");
}

__global__ __launch_bounds__(THR_)
void fused_kernel(const float* __restrict__ x,
                  const float* __restrict__ gt,
                  const float* __restrict__ t_p,
                  const float* __restrict__ ct,
                  float* __restrict__ out) {
    // two staging buffers; phase-1 reduce arrays are overlaid on them (dead after)
    __shared__ __align__(16) float smem_t[2][TILE_ * TSTR_];   // 33.8 KB
    __shared__ int s_plane[128];
    __shared__ int s_cls;

    float4* sv4 = (float4*)smem_t[0];      // 512 * 16B = 8 KB (fits in buf0)
    int4*   si4 = (int4*)smem_t[1];        // 8 KB (fits in buf1)

    const int tid  = threadIdx.x;
    const int lane = tid & 31;             // float4 channel-group
    const int hwg  = tid >> 5;             // warp id == hw group (0..15)
    const int b    = blockIdx.y;
    const int c4   = blockIdx.x * 32 + lane;

    const float4* x4 = (const float4*)x;
    const size_t bb4 = (size_t)b * HWN_ * C4_;

    // staging helper: warp hwg stages channels [hwg*8, hwg*8+8) of tile T into buf
    auto stage = [&](int T, float* buf) {
        const int hw0s = T * TILE_;
        const bool p = (hw0s + lane) < HWN_ && lane < TILE_;
        #pragma unroll
        for (int j = 0; j < 8; ++j) {
            int ch = hwg * 8 + j;
            unsigned dst = (unsigned)__cvta_generic_to_shared(&buf[lane * TSTR_ + ch]);
            cp_async4(dst, t_p + s_plane[ch] + hw0s + lane, p);
        }
    };

    // ---- cls[b] = argmax(gt[b,:200]) — warp 0 via shfl ----
    if (hwg == 0) {
        const float* g = gt + (size_t)b * NCLS_;
        float bv = -1e30f; int bi = NCLS_;
        for (int i = lane; i < NCLS_; i += 32) {
            float v = __ldg(g + i);
            if (v > bv) { bv = v; bi = i; }
        }
        #pragma unroll
        for (int s = 16; s > 0; s >>= 1) {
            float ov = __shfl_down_sync(0xffffffffu, bv, s);
            int   oi = __shfl_down_sync(0xffffffffu, bi, s);
            if (ov > bv || (ov == bv && oi < bi)) { bv = ov; bi = oi; }
        }
        if (lane == 0) s_cls = bi;
    }

    // ---- phase 1: spatial argmax; 4 channels/thread, hw interleaved by 16 ----
    float mv[4] = {-1e30f, -1e30f, -1e30f, -1e30f};
    int   mi[4] = {0, 0, 0, 0};
    for (int hw = hwg; hw < HWN_; hw += NWRP_) {
        float4 v = __ldg(&x4[bb4 + (size_t)hw * C4_ + c4]);
        if (v.x > mv[0]) { mv[0] = v.x; mi[0] = hw; }
        if (v.y > mv[1]) { mv[1] = v.y; mi[1] = hw; }
        if (v.z > mv[2]) { mv[2] = v.z; mi[2] = hw; }
        if (v.w > mv[3]) { mv[3] = v.w; mi[3] = hw; }
    }
    sv4[tid] = make_float4(mv[0], mv[1], mv[2], mv[3]);
    si4[tid] = make_int4(mi[0], mi[1], mi[2], mi[3]);
    __syncthreads();

    if (tid < 32) {
        float bm[4] = {-1e30f, -1e30f, -1e30f, -1e30f};
        int   bx[4] = {0, 0, 0, 0};
        #pragma unroll
        for (int g2 = 0; g2 < NWRP_; ++g2) {
            float4 v = sv4[g2 * 32 + tid];
            int4   i = si4[g2 * 32 + tid];
            if (v.x > bm[0] || (v.x == bm[0] && i.x < bx[0])) { bm[0]=v.x; bx[0]=i.x; }
            if (v.y > bm[1] || (v.y == bm[1] && i.y < bx[1])) { bm[1]=v.y; bx[1]=i.y; }
            if (v.z > bm[2] || (v.z == bm[2] && i.z < bx[2])) { bm[2]=v.z; bx[2]=i.z; }
            if (v.w > bm[3] || (v.w == bm[3] && i.w < bx[3])) { bm[3]=v.w; bx[3]=i.w; }
        }
        #pragma unroll
        for (int i = 0; i < 4; ++i) {
            int hh = bx[i] / W_;
            int ww = bx[i] - hh * W_;
            if (bm[i] == 0.0f) { hh = H_; ww = W_; }   // sentinel
            s_plane[tid * 4 + i] = (hh * (W_ + 1) + ww) * HWN_;
        }
    }
    __syncthreads();   // s_plane ready; reduce arrays now dead -> buffers reusable

    // ---- phase 2: cp.async double-buffered template staging + elementwise ----
    const int cls = s_cls;
    const float4* ct4 = (const float4*)ct;
    const size_t ctb4 = (size_t)cls * HWN_ * C4_ + c4;
    const size_t psz4 = (size_t)B_ * HWN_ * C4_;
    float4* o4 = (float4*)out;

    stage(0, smem_t[0]); cp_commit();
    stage(1, smem_t[1]); cp_commit();

    for (int t = 0; t < NT_; ++t) {
        cp_wait<1>();          // tile t staged (tile t+1 may still be in flight)
        __syncthreads();       // all warps' staged data visible

        const float* buf = smem_t[t & 1];
        const int hw0 = t * TILE_;
        const int rows = (HWN_ - hw0 < TILE_) ? (HWN_ - hw0) : TILE_;

        const int k0 = hwg;
        const int k1 = hwg + 16;
        if (k0 < rows) {
            const size_t off = bb4 + (size_t)(hw0 + k0) * C4_ + c4;
            float4 xv = __ldg(&x4[off]);
            float4 cv = __ldg(&ct4[ctb4 + (size_t)(hw0 + k0) * C4_]);
            float4 tv = *(const float4*)&buf[k0 * TSTR_ + lane * 4];
            float4 m;
            m.x = fmaxf(xv.x * tv.x, 0.0f) * cv.x;
            m.y = fmaxf(xv.y * tv.y, 0.0f) * cv.y;
            m.z = fmaxf(xv.z * tv.z, 0.0f) * cv.z;
            m.w = fmaxf(xv.w * tv.w, 0.0f) * cv.w;
            o4[off]            = m;
            o4[psz4 + off]     = xv;
            o4[2 * psz4 + off] = tv;
        }
        if (k1 < rows) {
            const size_t off = bb4 + (size_t)(hw0 + k1) * C4_ + c4;
            float4 xv = __ldg(&x4[off]);
            float4 cv = __ldg(&ct4[ctb4 + (size_t)(hw0 + k1) * C4_]);
            float4 tv = *(const float4*)&buf[k1 * TSTR_ + lane * 4];
            float4 m;
            m.x = fmaxf(xv.x * tv.x, 0.0f) * cv.x;
            m.y = fmaxf(xv.y * tv.y, 0.0f) * cv.y;
            m.z = fmaxf(xv.z * tv.z, 0.0f) * cv.z;
            m.w = fmaxf(xv.w * tv.w, 0.0f) * cv.w;
            o4[off]            = m;
            o4[psz4 + off]     = xv;
            o4[2 * psz4 + off] = tv;
        }
        __syncthreads();       // everyone done reading buf[t&1] before restage

        if (t + 2 < NT_) stage(t + 2, smem_t[t & 1]);
        cp_commit();           // always commit (possibly empty group)
    }
}

extern "C" void kernel_launch(void* const* d_in, const int* in_sizes, int n_in,
                              void* d_out, int out_size) {
    const float* x  = (const float*)d_in[0];
    const float* gt = (const float*)d_in[1];
    const float* tp = (const float*)d_in[2];
    const float* ct = (const float*)d_in[3];
    float* out = (float*)d_out;

    fused_kernel<<<dim3(C4_ / 32, B_), THR_>>>(x, gt, tp, ct, out);
}

// round 11
// speedup vs baseline: 1.0665x; 1.0665x over previous
#include <cuda_runtime.h>
#include <cuda_bf16.h>
#include <cstdint>

#define B_    128
#define H_    14
#define W_    14
#define C4_   128           // C/4
#define NCLS_ 200
#define HWN_  196
#define TILE_ 28
#define NT_   7
#define TSTR_ 132           // row stride (floats): 528 B, 16B multiple -> aligned LDS.128
#define THR_  512
#define NWRP_ 16

__global__ __launch_bounds__(THR_, 3)
void fused_kernel(const float* __restrict__ x,
                  const float* __restrict__ gt,
                  const float* __restrict__ t_p,
                  const float* __restrict__ ct,
                  float* __restrict__ out) {
    // double-buffered staging; phase-1 reduce arrays overlaid (dead after phase 1)
    __shared__ __align__(16) float smem_t[2][TILE_ * TSTR_];   // 29.6 KB
    __shared__ int s_plane[128];
    __shared__ int s_cls;

    float4* sv4 = (float4*)smem_t[0];      // 8 KB
    int4*   si4 = (int4*)smem_t[1];        // 8 KB

    const int tid  = threadIdx.x;
    const int lane = tid & 31;             // float4 channel-group
    const int hwg  = tid >> 5;             // warp id (0..15)
    const int b    = blockIdx.y;
    const int c4   = blockIdx.x * 32 + lane;

    const float4* x4 = (const float4*)x;
    const size_t bb4 = (size_t)b * HWN_ * C4_;

    // ---- cls[b] = argmax(gt[b,:200]) — warp 0 via shfl ----
    if (hwg == 0) {
        const float* g = gt + (size_t)b * NCLS_;
        float bv = -1e30f; int bi = NCLS_;
        for (int i = lane; i < NCLS_; i += 32) {
            float v = __ldg(g + i);
            if (v > bv) { bv = v; bi = i; }
        }
        #pragma unroll
        for (int s = 16; s > 0; s >>= 1) {
            float ov = __shfl_down_sync(0xffffffffu, bv, s);
            int   oi = __shfl_down_sync(0xffffffffu, bi, s);
            if (ov > bv || (ov == bv && oi < bi)) { bv = ov; bi = oi; }
        }
        if (lane == 0) s_cls = bi;
    }

    // ---- phase 1: spatial argmax; 4 channels/thread, hw interleaved by 16 ----
    float mv[4] = {-1e30f, -1e30f, -1e30f, -1e30f};
    int   mi[4] = {0, 0, 0, 0};
    for (int hw = hwg; hw < HWN_; hw += NWRP_) {
        float4 v = __ldg(&x4[bb4 + (size_t)hw * C4_ + c4]);
        if (v.x > mv[0]) { mv[0] = v.x; mi[0] = hw; }
        if (v.y > mv[1]) { mv[1] = v.y; mi[1] = hw; }
        if (v.z > mv[2]) { mv[2] = v.z; mi[2] = hw; }
        if (v.w > mv[3]) { mv[3] = v.w; mi[3] = hw; }
    }
    sv4[tid] = make_float4(mv[0], mv[1], mv[2], mv[3]);
    si4[tid] = make_int4(mi[0], mi[1], mi[2], mi[3]);
    __syncthreads();

    if (tid < 32) {
        float bm[4] = {-1e30f, -1e30f, -1e30f, -1e30f};
        int   bx[4] = {0, 0, 0, 0};
        #pragma unroll
        for (int g2 = 0; g2 < NWRP_; ++g2) {
            float4 v = sv4[g2 * 32 + tid];
            int4   i = si4[g2 * 32 + tid];
            if (v.x > bm[0] || (v.x == bm[0] && i.x < bx[0])) { bm[0]=v.x; bx[0]=i.x; }
            if (v.y > bm[1] || (v.y == bm[1] && i.y < bx[1])) { bm[1]=v.y; bx[1]=i.y; }
            if (v.z > bm[2] || (v.z == bm[2] && i.z < bx[2])) { bm[2]=v.z; bx[2]=i.z; }
            if (v.w > bm[3] || (v.w == bm[3] && i.w < bx[3])) { bm[3]=v.w; bx[3]=i.w; }
        }
        #pragma unroll
        for (int i = 0; i < 4; ++i) {
            int hh = bx[i] / W_;
            int ww = bx[i] - hh * W_;
            if (bm[i] == 0.0f) { hh = H_; ww = W_; }   // sentinel
            s_plane[tid * 4 + i] = (hh * (W_ + 1) + ww) * HWN_;
        }
    }
    __syncthreads();   // s_plane ready; reduce overlay dead -> buffers reusable

    // ---- phase 2: register-pipelined staging + vectorized elementwise ----
    const int cls = s_cls;
    const float4* ct4 = (const float4*)ct;
    const size_t ctb4 = (size_t)cls * HWN_ * C4_ + c4;
    const size_t psz4 = (size_t)B_ * HWN_ * C4_;
    float4* o4 = (float4*)out;

    // each warp stages 8 channels [hwg*8, hwg*8+8); lanes 0..27 carry one hw each
    const bool sp = lane < TILE_;
    int ch0 = hwg * 8;
    float treg[8];

    // prologue: gather tile 0 into registers
    #pragma unroll
    for (int j = 0; j < 8; ++j)
        treg[j] = sp ? __ldg(t_p + s_plane[ch0 + j] + lane) : 0.0f;

    for (int t = 0; t < NT_; ++t) {
        // store staged regs for tile t
        float* buf = smem_t[t & 1];
        if (sp) {
            #pragma unroll
            for (int j = 0; j < 8; ++j)
                buf[lane * TSTR_ + ch0 + j] = treg[j];
        }
        __syncthreads();

        // issue gather for tile t+1 (latency hidden under compute below)
        if (t + 1 < NT_) {
            const int hw0n = (t + 1) * TILE_;
            #pragma unroll
            for (int j = 0; j < 8; ++j)
                treg[j] = sp ? __ldg(t_p + s_plane[ch0 + j] + hw0n + lane) : 0.0f;
        }

        // compute tile t
        const int hw0 = t * TILE_;
        for (int k = hwg; k < TILE_; k += NWRP_) {
            const int hw = hw0 + k;
            const size_t off = bb4 + (size_t)hw * C4_ + c4;
            float4 xv = __ldg(&x4[off]);
            float4 cv = __ldg(&ct4[ctb4 + (size_t)hw * C4_]);
            float4 tv = *(const float4*)&buf[k * TSTR_ + lane * 4];
            float4 m;
            m.x = fmaxf(xv.x * tv.x, 0.0f) * cv.x;
            m.y = fmaxf(xv.y * tv.y, 0.0f) * cv.y;
            m.z = fmaxf(xv.z * tv.z, 0.0f) * cv.z;
            m.w = fmaxf(xv.w * tv.w, 0.0f) * cv.w;
            o4[off]            = m;
            o4[psz4 + off]     = xv;
            o4[2 * psz4 + off] = tv;
        }
        // no trailing barrier: buf[t&1] is next written at t+2, and the
        // barrier at t+1 orders all tile-t reads before those writes.
    }
}

extern "C" void kernel_launch(void* const* d_in, const int* in_sizes, int n_in,
                              void* d_out, int out_size) {
    const float* x  = (const float*)d_in[0];
    const float* gt = (const float*)d_in[1];
    const float* tp = (const float*)d_in[2];
    const float* ct = (const float*)d_in[3];
    float* out = (float*)d_out;

    fused_kernel<<<dim3(C4_ / 32, B_), THR_>>>(x, gt, tp, ct, out);
}